// round 8
// baseline (speedup 1.0000x reference)
#include <cuda_runtime.h>
#include <cuda_fp16.h>
#include <cstdint>

// ---------------- problem constants ----------------
constexpr int NODES  = 100000;
constexpr int EDGES  = 500000;
constexpr int FEAT   = 256;
constexpr int CLASSES = 349;
constexpr int NPAD_OUT = 384;
constexpr float NEG_SLOPE = 0.2f;
constexpr int GRID_M = (NODES + 127) / 128;   // 782

// GEMM tiling
constexpr int STAGES = 3;
constexpr int TILE_BYTES = 128 * 80;
constexpr int STAGE_BYTES = 2 * TILE_BYTES;
constexpr int GEMM_SMEM = STAGES * STAGE_BYTES + 2048;   // tiles + el/er accum
constexpr int STRIPE = 4;

// side-task block counts
constexpr int N1_F4 = 3 * NODES * FEAT / 4;   // agg zero (float4 count)
constexpr int N2_F4 = 3 * NODES * 4 / 4;      // denom zero
constexpr int ZERO_BLOCKS = (N1_F4 + N2_F4 + 255) / 256;
constexpr int EDGE_BLOCKS = (EDGES + 7) / 8;  // 8 edges (warps) per block

// ---------------- device scratch ----------------
__device__ float  g_feat[(size_t)2 * NODES * FEAT];   // double-buffered per etype
__device__ float  g_agg[(size_t)3 * NODES * FEAT];    // per-etype unnormalized agg
__device__ float  g_el[3 * NODES * 4];
__device__ float  g_er[3 * NODES * 4];
__device__ float  g_den[3 * NODES * 4];
__device__ __half g_ahi[(size_t)NODES * FEAT];
__device__ __half g_alo[(size_t)NODES * FEAT];
__device__ __half g_whi[6 * FEAT * FEAT];
__device__ __half g_wohi[NPAD_OUT * FEAT];

// ---------------- helpers ----------------
__device__ __forceinline__ void red4(float* p, float a, float b, float c, float d) {
    asm volatile("red.global.add.v4.f32 [%0], {%1,%2,%3,%4};"
                 :: "l"(p), "f"(a), "f"(b), "f"(c), "f"(d) : "memory");
}
__device__ __forceinline__ uint32_t smem_u32(const void* p) {
    uint32_t a;
    asm("{ .reg .u64 t; cvta.to.shared.u64 t, %1; cvt.u32.u64 %0, t; }" : "=r"(a) : "l"(p));
    return a;
}
__device__ __forceinline__ void cp16(uint32_t dst, const void* src, uint32_t sz) {
    asm volatile("cp.async.cg.shared.global [%0], [%1], 16, %2;"
                 :: "r"(dst), "l"(src), "r"(sz) : "memory");
}
__device__ __forceinline__ void cp_commit() { asm volatile("cp.async.commit_group;" ::: "memory"); }
__device__ __forceinline__ void cp_wait1()  { asm volatile("cp.async.wait_group 1;" ::: "memory"); }
__device__ __forceinline__ void cp_wait0()  { asm volatile("cp.async.wait_group 0;" ::: "memory"); }

__device__ __forceinline__ void ldmx4(uint32_t* r, uint32_t addr) {
    asm volatile("ldmatrix.sync.aligned.m8n8.x4.shared.b16 {%0,%1,%2,%3}, [%4];"
                 : "=r"(r[0]), "=r"(r[1]), "=r"(r[2]), "=r"(r[3]) : "r"(addr));
}
__device__ __forceinline__ void mma16816(float* d, const uint32_t* a,
                                         uint32_t b0, uint32_t b1) {
    asm volatile(
        "mma.sync.aligned.m16n8k16.row.col.f32.f16.f16.f32 "
        "{%0,%1,%2,%3}, {%4,%5,%6,%7}, {%8,%9}, {%0,%1,%2,%3};"
        : "+f"(d[0]), "+f"(d[1]), "+f"(d[2]), "+f"(d[3])
        : "r"(a[0]), "r"(a[1]), "r"(a[2]), "r"(a[3]), "r"(b0), "r"(b1));
}

// ---------------- fused exp + aggregation (per edge warp) ----------------
__device__ __forceinline__ void edge_body(
    int eidx, int tid,
    const int* __restrict__ se, const int* __restrict__ de,
    const float* __restrict__ elP, const float* __restrict__ erP,
    float* __restrict__ denP, const float* __restrict__ featP,
    float* __restrict__ aggP)
{
    int warp = eidx * 8 + (tid >> 5);
    if (warp >= EDGES) return;
    int lane = tid & 31;
    int s = se[warp], d = de[warp];
    float exv = 0.f;
    if (lane < 4) {
        float lg = elP[(size_t)s * 4 + lane] + erP[(size_t)d * 4 + lane];
        lg = lg > 0.f ? lg : NEG_SLOPE * lg;
        exv = __expf(lg);
        atomicAdd(denP + (size_t)d * 4 + lane, exv);
    }
    int h0 = lane >> 4;
    float e0 = __shfl_sync(0xffffffffu, exv, h0);
    float e1 = __shfl_sync(0xffffffffu, exv, h0 + 2);
    const float4* fs = reinterpret_cast<const float4*>(featP + (size_t)s * FEAT);
    float4 f0 = fs[lane];
    float4 f1 = fs[lane + 32];
    float* base = aggP + (size_t)d * FEAT;
    red4(base + lane * 4,       e0 * f0.x, e0 * f0.y, e0 * f0.z, e0 * f0.w);
    red4(base + 128 + lane * 4, e1 * f1.x, e1 * f1.y, e1 * f1.z, e1 * f1.w);
}

// ---------------- merged mega kernel: GEMM (+att epi) and a side task -------
// sideMode: 0 = none, 1 = zero-fill (z1/n1, z2/n2), 2 = edge aggregation
__global__ void __launch_bounds__(256, 2) mega(
    const __half* __restrict__ Ahi, const __half* __restrict__ Alo,
    const __half* __restrict__ B, float* __restrict__ C,
    const float* __restrict__ bias, int M, int Ncols, int gy,
    const float* __restrict__ al, const float* __restrict__ ar,
    float* __restrict__ elO, float* __restrict__ erO,
    int sideMode,
    float* __restrict__ z1, int n1, float* __restrict__ z2, int n2,
    const int* __restrict__ se, const int* __restrict__ de,
    const float* __restrict__ elP, const float* __restrict__ erP,
    float* __restrict__ denP, const float* __restrict__ featP,
    float* __restrict__ aggP)
{
    const int tid = threadIdx.x;
    const int bid = blockIdx.x;
    const int gB = GRID_M * gy;

    int role = 0, idx = bid;
    if (sideMode != 0) {
        int lim = gB * STRIPE;
        if (bid < lim) {
            if ((bid % STRIPE) == 0) { role = 0; idx = bid / STRIPE; }
            else                     { role = 1; idx = bid - bid / STRIPE - 1; }
        } else { role = 1; idx = bid - gB; }
    }

    if (role == 1) {
        if (sideMode == 1) {
            int i = idx * 256 + tid;
            if (i < n1) reinterpret_cast<float4*>(z1)[i] = make_float4(0.f, 0.f, 0.f, 0.f);
            else {
                int j = i - n1;
                if (j < n2) reinterpret_cast<float4*>(z2)[j] = make_float4(0.f, 0.f, 0.f, 0.f);
            }
        } else {
            edge_body(idx, tid, se, de, elP, erP, denP, featP, aggP);
        }
        return;
    }

    // ---------------- GEMM body ----------------
    extern __shared__ char smem[];
    const uint32_t sbase = smem_u32(smem);
    const int lane = tid & 31;
    const int warp = tid >> 5;
    const int wm = (warp & 1) * 64;
    const int wn = (warp >> 1) * 32;
    const long bm = (long)(idx % GRID_M) * 128;
    const int bn  = (idx / GRID_M) * 128;

    float acc[4][4][4];
#pragma unroll
    for (int i = 0; i < 4; i++)
#pragma unroll
        for (int j = 0; j < 4; j++)
#pragma unroll
            for (int q = 0; q < 4; q++) acc[i][j][q] = 0.f;

    const int NITER = 16;   // 2 passes (Ahi, Alo) x 8 k-chunks of 32

    auto issue = [&](int it) {
        const int p  = it >> 3;
        const int kc = it & 7;
        const __half* Ag = (p == 0) ? Ahi : Alo;
        const uint32_t sa = sbase + (it % STAGES) * STAGE_BYTES;
        const uint32_t sb = sa + TILE_BYTES;
#pragma unroll
        for (int q = 0; q < 2; q++) {
            int ix = tid * 2 + q;
            int row = ix >> 2;
            int ch  = ix & 3;
            long arow = bm + row;
            long arc = arow < (M - 1) ? arow : (M - 1);
            cp16(sa + row * 80 + ch * 16, Ag + arc * 256 + kc * 32 + ch * 8,
                 (arow < M) ? 16u : 0u);
            cp16(sb + row * 80 + ch * 16, B + (long)(bn + row) * 256 + kc * 32 + ch * 8, 16u);
        }
        cp_commit();
    };

    issue(0);
    issue(1);

    for (int it = 0; it < NITER; it++) {
        cp_wait1();
        __syncthreads();
        if (it + 2 < NITER) issue(it + 2);

        const uint32_t sa = sbase + (it % STAGES) * STAGE_BYTES;
        const uint32_t sb = sa + TILE_BYTES;
#pragma unroll
        for (int ks = 0; ks < 2; ks++) {
            uint32_t a[4][4];
#pragma unroll
            for (int mt = 0; mt < 4; mt++)
                ldmx4(a[mt], sa + (wm + mt * 16 + (lane & 15)) * 80
                              + ks * 32 + (lane >> 4) * 16);
            uint32_t b[2][4];
#pragma unroll
            for (int jb = 0; jb < 2; jb++)
                ldmx4(b[jb], sb + (wn + jb * 16 + ((lane >> 4) << 3) + (lane & 7)) * 80
                              + ks * 32 + ((lane >> 3) & 1) * 16);
#pragma unroll
            for (int mt = 0; mt < 4; mt++)
#pragma unroll
                for (int nt = 0; nt < 4; nt++)
                    mma16816(acc[mt][nt], a[mt],
                             b[nt >> 1][(nt & 1) * 2], b[nt >> 1][(nt & 1) * 2 + 1]);
        }
        __syncthreads();
    }
    cp_wait0();

    // ---------------- epilogue (+ fused attention dots) ----------------
    float* elacc = reinterpret_cast<float*>(smem + STAGES * STAGE_BYTES);  // [128][2]
    float* eracc = elacc + 256;
    float alv[8], arv[8];
    float pel[4][2] = {}, per_[4][2] = {};
    if (al) {
        if (tid < 256) { elacc[tid] = 0.f; eracc[tid] = 0.f; }
        __syncthreads();
#pragma unroll
        for (int nt = 0; nt < 4; nt++) {
            int c0 = bn + wn + nt * 8 + (lane & 3) * 2;
            alv[nt * 2]     = al[c0];
            alv[nt * 2 + 1] = al[c0 + 1];
            arv[nt * 2]     = ar[c0];
            arv[nt * 2 + 1] = ar[c0 + 1];
        }
    }

    const bool even = ((Ncols & 1) == 0);
#pragma unroll
    for (int mt = 0; mt < 4; mt++) {
#pragma unroll
        for (int nt = 0; nt < 4; nt++) {
            int c0 = bn + wn + nt * 8 + (lane & 3) * 2;
            float b0 = 0.f, b1 = 0.f;
            if (bias) {
                if (c0 < Ncols)     b0 = bias[c0];
                if (c0 + 1 < Ncols) b1 = bias[c0 + 1];
            }
#pragma unroll
            for (int half = 0; half < 2; half++) {
                long row = bm + wm + mt * 16 + (lane >> 2) + half * 8;
                float v0 = acc[mt][nt][half * 2 + 0];
                float v1 = acc[mt][nt][half * 2 + 1];
                if (al) {
                    pel[mt][half]  += v0 * alv[nt * 2] + v1 * alv[nt * 2 + 1];
                    per_[mt][half] += v0 * arv[nt * 2] + v1 * arv[nt * 2 + 1];
                }
                if (row >= M) continue;
                v0 += b0; v1 += b1;
                float* crow = C + row * Ncols;
                if (even && (c0 + 1) < Ncols) {
                    *reinterpret_cast<float2*>(crow + c0) = make_float2(v0, v1);
                } else {
                    if (c0 < Ncols)     crow[c0] = v0;
                    if (c0 + 1 < Ncols) crow[c0 + 1] = v1;
                }
            }
        }
    }

    if (al) {
#pragma unroll
        for (int mt = 0; mt < 4; mt++)
#pragma unroll
            for (int half = 0; half < 2; half++) {
                float s1 = pel[mt][half], s2 = per_[mt][half];
                s1 += __shfl_xor_sync(0xffffffffu, s1, 1);
                s1 += __shfl_xor_sync(0xffffffffu, s1, 2);
                s2 += __shfl_xor_sync(0xffffffffu, s2, 1);
                s2 += __shfl_xor_sync(0xffffffffu, s2, 2);
                if ((lane & 3) == 0) {
                    int rl = wm + mt * 16 + (lane >> 2) + half * 8;
                    int hl = wn >> 6;
                    atomicAdd(&elacc[rl * 2 + hl], s1);
                    atomicAdd(&eracc[rl * 2 + hl], s2);
                }
            }
        __syncthreads();
        if (tid < 256) {
            int rl = tid >> 1, hl = tid & 1;
            long n = bm + rl;
            if (n < M) {
                int hg = (bn >> 6) + hl;
                elO[n * 4 + hg] = elacc[tid];
                erO[n * 4 + hg] = eracc[tid];
            }
        }
    }
}

// ---------------- standalone edge kernel (high occupancy) ----------------
__global__ void __launch_bounds__(256) edge_kernel(
    const int* __restrict__ se, const int* __restrict__ de,
    const float* __restrict__ elP, const float* __restrict__ erP,
    float* __restrict__ denP, const float* __restrict__ featP,
    float* __restrict__ aggP)
{
    edge_body(blockIdx.x, threadIdx.x, se, de, elP, erP, denP, featP, aggP);
}

// ---------------- finalize: h = act(sum_e agg_e/den_e + bias) -> fp16 split ----
__global__ void __launch_bounds__(256) finalize3(
    const float* __restrict__ agg, const float* __restrict__ den,
    const float* __restrict__ bias_l,
    __half* __restrict__ hi, __half* __restrict__ lo, int do_relu)
{
    int i = blockIdx.x * 256 + threadIdx.x;     // float4 index
    if (i >= NODES * 64) return;
    int n = i >> 6;
    int h = (i >> 4) & 3;
    int c = (i & 63) * 4;
    const float4* a4 = reinterpret_cast<const float4*>(agg);
    float4 v = make_float4(0.f, 0.f, 0.f, 0.f);
#pragma unroll
    for (int e = 0; e < 3; e++) {
        float4 a = a4[(size_t)e * NODES * 64 + i];
        float dv = den[(size_t)e * NODES * 4 + n * 4 + h];
        float r = (dv > 0.f) ? (1.0f / dv) : 0.f;   // empty segment -> 0 (matches segment_sum)
        v.x += a.x * r; v.y += a.y * r; v.z += a.z * r; v.w += a.w * r;
    }
    v.x += bias_l[c]     + bias_l[256 + c]     + bias_l[512 + c];
    v.y += bias_l[c + 1] + bias_l[256 + c + 1] + bias_l[512 + c + 1];
    v.z += bias_l[c + 2] + bias_l[256 + c + 2] + bias_l[512 + c + 2];
    v.w += bias_l[c + 3] + bias_l[256 + c + 3] + bias_l[512 + c + 3];
    if (do_relu) {
        v.x = fmaxf(v.x, 0.f); v.y = fmaxf(v.y, 0.f);
        v.z = fmaxf(v.z, 0.f); v.w = fmaxf(v.w, 0.f);
    }
    __half h0 = __float2half_rn(v.x), h1 = __float2half_rn(v.y);
    __half h2 = __float2half_rn(v.z), h3 = __float2half_rn(v.w);
    __half l0 = __float2half_rn(v.x - __half2float(h0));
    __half l1 = __float2half_rn(v.y - __half2float(h1));
    __half l2 = __float2half_rn(v.z - __half2float(h2));
    __half l3 = __float2half_rn(v.w - __half2float(h3));
    __half2* ph = reinterpret_cast<__half2*>(hi);
    __half2* pl = reinterpret_cast<__half2*>(lo);
    ph[i * 2]     = __halves2half2(h0, h1);
    ph[i * 2 + 1] = __halves2half2(h2, h3);
    pl[i * 2]     = __halves2half2(l0, l1);
    pl[i * 2 + 1] = __halves2half2(l2, l3);
}

// ---------------- prep kernels ----------------
__global__ void __launch_bounds__(256) split_f32(
    const float* __restrict__ in, __half* __restrict__ hi,
    __half* __restrict__ lo, int n4)
{
    int i = blockIdx.x * blockDim.x + threadIdx.x;
    if (i >= n4) return;
    float4 v = reinterpret_cast<const float4*>(in)[i];
    __half h0 = __float2half_rn(v.x), h1 = __float2half_rn(v.y);
    __half h2 = __float2half_rn(v.z), h3 = __float2half_rn(v.w);
    __half l0 = __float2half_rn(v.x - __half2float(h0));
    __half l1 = __float2half_rn(v.y - __half2float(h1));
    __half l2 = __float2half_rn(v.z - __half2float(h2));
    __half l3 = __float2half_rn(v.w - __half2float(h3));
    __half2* ph = reinterpret_cast<__half2*>(hi);
    __half2* pl = reinterpret_cast<__half2*>(lo);
    ph[i * 2]     = __halves2half2(h0, h1);
    ph[i * 2 + 1] = __halves2half2(h2, h3);
    pl[i * 2]     = __halves2half2(l0, l1);
    pl[i * 2 + 1] = __halves2half2(l2, l3);
}

__global__ void __launch_bounds__(256) prep_w(
    const float* __restrict__ W, __half* __restrict__ hi)
{
    int idx = blockIdx.x * blockDim.x + threadIdx.x;
    if (idx >= 6 * FEAT * FEAT) return;
    int le = idx >> 16;
    int r  = idx & 0xffff;
    int n  = r >> 8;
    int k  = r & 255;
    hi[le * FEAT * FEAT + n * FEAT + k] = __float2half_rn(W[le * FEAT * FEAT + k * FEAT + n]);
}

__global__ void __launch_bounds__(256) prep_wout(
    const float* __restrict__ W_out, __half* __restrict__ hi)
{
    int idx = blockIdx.x * blockDim.x + threadIdx.x;
    if (idx >= NPAD_OUT * FEAT) return;
    int n = idx >> 8;
    int k = idx & 255;
    float v = (n < CLASSES) ? W_out[k * CLASSES + n] : 0.f;
    hi[n * FEAT + k] = __float2half_rn(v);
}

// ---------------- launch ----------------
extern "C" void kernel_launch(void* const* d_in, const int* in_sizes, int n_in,
                              void* d_out, int out_size)
{
    const float* x      = (const float*)d_in[0];
    const float* W      = (const float*)d_in[1];
    const float* attn_l = (const float*)d_in[2];
    const float* attn_r = (const float*)d_in[3];
    const float* bias   = (const float*)d_in[4];
    const float* W_out  = (const float*)d_in[5];
    const float* b_out  = (const float*)d_in[6];
    const int*   src    = (const int*)d_in[7];
    const int*   dst    = (const int*)d_in[8];

    float *feat, *agg, *el, *er, *den;
    __half *ahi, *alo, *whi, *wohi;
    cudaGetSymbolAddress((void**)&feat, g_feat);
    cudaGetSymbolAddress((void**)&agg,  g_agg);
    cudaGetSymbolAddress((void**)&el,   g_el);
    cudaGetSymbolAddress((void**)&er,   g_er);
    cudaGetSymbolAddress((void**)&den,  g_den);
    cudaGetSymbolAddress((void**)&ahi,  g_ahi);
    cudaGetSymbolAddress((void**)&alo,  g_alo);
    cudaGetSymbolAddress((void**)&whi,  g_whi);
    cudaGetSymbolAddress((void**)&wohi, g_wohi);

    cudaFuncSetAttribute(mega, cudaFuncAttributeMaxDynamicSharedMemorySize, GEMM_SMEM);

    prep_w<<<(6 * FEAT * FEAT + 255) / 256, 256>>>(W, whi);
    prep_wout<<<(NPAD_OUT * FEAT + 255) / 256, 256>>>(W_out, wohi);
    split_f32<<<(NODES * FEAT / 4 + 255) / 256, 256>>>(x, ahi, alo, NODES * FEAT / 4);

    for (int l = 0; l < 2; l++) {
        for (int e = 0; e < 3; e++) {
            int le = l * 3 + e;
            float* feat_e = feat + (size_t)(e & 1) * NODES * FEAT;
            int gB = GRID_M * 2;
            if (e == 0) {
                int T = gB + ZERO_BLOCKS;
                mega<<<T, 256, GEMM_SMEM>>>(
                    ahi, alo, whi + (size_t)le * FEAT * FEAT, feat_e, nullptr,
                    NODES, FEAT, 2,
                    attn_l + le * FEAT, attn_r + le * FEAT,
                    el + (size_t)e * NODES * 4, er + (size_t)e * NODES * 4,
                    1, agg, N1_F4, den, N2_F4,
                    nullptr, nullptr, nullptr, nullptr, nullptr, nullptr, nullptr);
            } else {
                int pe = e - 1;
                int T = gB + EDGE_BLOCKS;
                mega<<<T, 256, GEMM_SMEM>>>(
                    ahi, alo, whi + (size_t)le * FEAT * FEAT, feat_e, nullptr,
                    NODES, FEAT, 2,
                    attn_l + le * FEAT, attn_r + le * FEAT,
                    el + (size_t)e * NODES * 4, er + (size_t)e * NODES * 4,
                    2, nullptr, 0, nullptr, 0,
                    src + (size_t)pe * EDGES, dst + (size_t)pe * EDGES,
                    el + (size_t)pe * NODES * 4, er + (size_t)pe * NODES * 4,
                    den + (size_t)pe * NODES * 4,
                    feat + (size_t)(pe & 1) * NODES * FEAT,
                    agg + (size_t)pe * NODES * FEAT);
            }
        }
        // last etype's aggregation (standalone, high occupancy)
        edge_kernel<<<EDGE_BLOCKS, 256>>>(
            src + (size_t)2 * EDGES, dst + (size_t)2 * EDGES,
            el + (size_t)2 * NODES * 4, er + (size_t)2 * NODES * 4,
            den + (size_t)2 * NODES * 4,
            feat,                                   // e=2 -> buffer 0
            agg + (size_t)2 * NODES * FEAT);
        finalize3<<<(NODES * 64 + 255) / 256, 256>>>(
            agg, den, bias + l * 3 * FEAT, ahi, alo, (l == 0) ? 1 : 0);
    }

    // output GEMM (no att epilogue, no side task)
    mega<<<GRID_M * 3, 256, GEMM_SMEM>>>(
        ahi, alo, wohi, (float*)d_out, b_out, NODES, CLASSES, 3,
        nullptr, nullptr, nullptr, nullptr,
        0, nullptr, 0, nullptr, 0,
        nullptr, nullptr, nullptr, nullptr, nullptr, nullptr, nullptr);
}

// round 9
// speedup vs baseline: 1.8942x; 1.8942x over previous
#include <cuda_runtime.h>
#include <cuda_fp16.h>
#include <cstdint>

// ---------------- problem constants ----------------
constexpr int NODES  = 100000;
constexpr int EDGES  = 500000;
constexpr int FEAT   = 256;
constexpr int CLASSES = 349;
constexpr int NPAD_OUT = 384;
constexpr float NEG_SLOPE = 0.2f;
constexpr int GRID_M = (NODES + 127) / 128;   // 782

constexpr int TOTE = 3 * EDGES;               // 1.5M
constexpr int NSEG = 3 * NODES;               // 300k
constexpr int SBLK = 512;
constexpr int NBLK = (NSEG + SBLK - 1) / SBLK; // 586

// GEMM tiling
constexpr int STAGES = 3;
constexpr int TILE_BYTES = 128 * 80;
constexpr int STAGE_BYTES = 2 * TILE_BYTES;
constexpr int GEMM_SMEM = STAGES * STAGE_BYTES + 2048;

// ---------------- device scratch ----------------
__device__ float  g_feat[(size_t)NODES * FEAT];
__device__ float  g_agg[(size_t)NODES * FEAT];
__device__ float  g_el[NODES * 4];
__device__ float  g_er[NODES * 4];
__device__ __half g_ahi[(size_t)NODES * FEAT];
__device__ __half g_alo[(size_t)NODES * FEAT];
__device__ __half g_whi[6 * FEAT * FEAT];
__device__ __half g_wohi[NPAD_OUT * FEAT];
__device__ int    g_rowptr[NSEG + 1];
__device__ int    g_head[NSEG];
__device__ int    g_blksum[NBLK];
__device__ int    g_ssorted[TOTE];

// ---------------- helpers ----------------
__device__ __forceinline__ uint32_t smem_u32(const void* p) {
    uint32_t a;
    asm("{ .reg .u64 t; cvta.to.shared.u64 t, %1; cvt.u32.u64 %0, t; }" : "=r"(a) : "l"(p));
    return a;
}
__device__ __forceinline__ void cp16(uint32_t dst, const void* src, uint32_t sz) {
    asm volatile("cp.async.cg.shared.global [%0], [%1], 16, %2;"
                 :: "r"(dst), "l"(src), "r"(sz) : "memory");
}
__device__ __forceinline__ void cp_commit() { asm volatile("cp.async.commit_group;" ::: "memory"); }
__device__ __forceinline__ void cp_wait1()  { asm volatile("cp.async.wait_group 1;" ::: "memory"); }
__device__ __forceinline__ void cp_wait0()  { asm volatile("cp.async.wait_group 0;" ::: "memory"); }

__device__ __forceinline__ void ldmx4(uint32_t* r, uint32_t addr) {
    asm volatile("ldmatrix.sync.aligned.m8n8.x4.shared.b16 {%0,%1,%2,%3}, [%4];"
                 : "=r"(r[0]), "=r"(r[1]), "=r"(r[2]), "=r"(r[3]) : "r"(addr));
}
__device__ __forceinline__ void mma16816(float* d, const uint32_t* a,
                                         uint32_t b0, uint32_t b1) {
    asm volatile(
        "mma.sync.aligned.m16n8k16.row.col.f32.f16.f16.f32 "
        "{%0,%1,%2,%3}, {%4,%5,%6,%7}, {%8,%9}, {%0,%1,%2,%3};"
        : "+f"(d[0]), "+f"(d[1]), "+f"(d[2]), "+f"(d[3])
        : "r"(a[0]), "r"(a[1]), "r"(a[2]), "r"(a[3]), "r"(b0), "r"(b1));
}

// ---------------- CSR build ----------------
__global__ void __launch_bounds__(256) zero_i(int* __restrict__ p, int n) {
    int i = blockIdx.x * 256 + threadIdx.x;
    if (i < n) p[i] = 0;
}

__global__ void __launch_bounds__(256) hist_k(const int* __restrict__ dst,
                                              int* __restrict__ counts) {
    int i = blockIdx.x * 256 + threadIdx.x;
    if (i >= TOTE) return;
    int e = i / EDGES;
    atomicAdd(&counts[e * NODES + dst[i]], 1);
}

__global__ void __launch_bounds__(SBLK) scan_l1(const int* __restrict__ counts,
                                                int* __restrict__ rowptr,
                                                int* __restrict__ blksum) {
    __shared__ int s[SBLK];
    int t = threadIdx.x, b = blockIdx.x, i = b * SBLK + t;
    int v = (i < NSEG) ? counts[i] : 0;
    s[t] = v;
    __syncthreads();
    for (int o = 1; o < SBLK; o <<= 1) {
        int x = (t >= o) ? s[t - o] : 0;
        __syncthreads();
        s[t] += x;
        __syncthreads();
    }
    if (i < NSEG) rowptr[i] = s[t] - v;
    if (t == SBLK - 1) blksum[b] = s[t];
}

__global__ void __launch_bounds__(1024) scan_l2(int* __restrict__ blksum,
                                                int* __restrict__ rowptr) {
    __shared__ int s[1024];
    int t = threadIdx.x;
    int v = (t < NBLK) ? blksum[t] : 0;
    s[t] = v;
    __syncthreads();
    for (int o = 1; o < 1024; o <<= 1) {
        int x = (t >= o) ? s[t - o] : 0;
        __syncthreads();
        s[t] += x;
        __syncthreads();
    }
    if (t < NBLK) blksum[t] = s[t] - v;
    if (t == 0) rowptr[NSEG] = TOTE;
}

__global__ void __launch_bounds__(256) scan_l3(int* __restrict__ rowptr,
                                               const int* __restrict__ blksum,
                                               int* __restrict__ head) {
    int i = blockIdx.x * 256 + threadIdx.x;
    if (i >= NSEG) return;
    int v = rowptr[i] + blksum[i / SBLK];
    rowptr[i] = v;
    head[i] = v;
}

__global__ void __launch_bounds__(256) scatter_k(const int* __restrict__ src,
                                                 const int* __restrict__ dst,
                                                 int* __restrict__ head,
                                                 int* __restrict__ ssorted) {
    int i = blockIdx.x * 256 + threadIdx.x;
    if (i >= TOTE) return;
    int e = i / EDGES;
    int pos = atomicAdd(&head[e * NODES + dst[i]], 1);
    ssorted[pos] = src[i];
}

// ---------------- prep kernels ----------------
__global__ void __launch_bounds__(256) split_f32(
    const float* __restrict__ in, __half* __restrict__ hi,
    __half* __restrict__ lo, int n4)
{
    int i = blockIdx.x * blockDim.x + threadIdx.x;
    if (i >= n4) return;
    float4 v = reinterpret_cast<const float4*>(in)[i];
    __half h0 = __float2half_rn(v.x), h1 = __float2half_rn(v.y);
    __half h2 = __float2half_rn(v.z), h3 = __float2half_rn(v.w);
    __half l0 = __float2half_rn(v.x - __half2float(h0));
    __half l1 = __float2half_rn(v.y - __half2float(h1));
    __half l2 = __float2half_rn(v.z - __half2float(h2));
    __half l3 = __float2half_rn(v.w - __half2float(h3));
    __half2* ph = reinterpret_cast<__half2*>(hi);
    __half2* pl = reinterpret_cast<__half2*>(lo);
    ph[i * 2]     = __halves2half2(h0, h1);
    ph[i * 2 + 1] = __halves2half2(h2, h3);
    pl[i * 2]     = __halves2half2(l0, l1);
    pl[i * 2 + 1] = __halves2half2(l2, l3);
}

__global__ void __launch_bounds__(256) prep_w(
    const float* __restrict__ W, __half* __restrict__ hi)
{
    int idx = blockIdx.x * blockDim.x + threadIdx.x;
    if (idx >= 6 * FEAT * FEAT) return;
    int le = idx >> 16;
    int r  = idx & 0xffff;
    int n  = r >> 8;
    int k  = r & 255;
    hi[le * FEAT * FEAT + n * FEAT + k] = __float2half_rn(W[le * FEAT * FEAT + k * FEAT + n]);
}

__global__ void __launch_bounds__(256) prep_wout(
    const float* __restrict__ W_out, __half* __restrict__ hi)
{
    int idx = blockIdx.x * blockDim.x + threadIdx.x;
    if (idx >= NPAD_OUT * FEAT) return;
    int n = idx >> 8;
    int k = idx & 255;
    float v = (n < CLASSES) ? W_out[k * CLASSES + n] : 0.f;
    hi[n * FEAT + k] = __float2half_rn(v);
}

// ---------------- tensor-core GEMM (+ fused attention dots) ----------------
__global__ void __launch_bounds__(256, 2) gemm_mma(
    const __half* __restrict__ Ahi, const __half* __restrict__ Alo,
    const __half* __restrict__ B, float* __restrict__ C,
    const float* __restrict__ bias, int M, int Ncols,
    const float* __restrict__ al, const float* __restrict__ ar,
    float* __restrict__ elO, float* __restrict__ erO)
{
    extern __shared__ char smem[];
    const uint32_t sbase = smem_u32(smem);
    const int tid = threadIdx.x;
    const int lane = tid & 31;
    const int warp = tid >> 5;
    const int wm = (warp & 1) * 64;
    const int wn = (warp >> 1) * 32;
    const long bm = (long)blockIdx.x * 128;
    const int bn  = blockIdx.y * 128;

    float acc[4][4][4];
#pragma unroll
    for (int i = 0; i < 4; i++)
#pragma unroll
        for (int j = 0; j < 4; j++)
#pragma unroll
            for (int q = 0; q < 4; q++) acc[i][j][q] = 0.f;

    const int NITER = 16;

    auto issue = [&](int it) {
        const int p  = it >> 3;
        const int kc = it & 7;
        const __half* Ag = (p == 0) ? Ahi : Alo;
        const uint32_t sa = sbase + (it % STAGES) * STAGE_BYTES;
        const uint32_t sb = sa + TILE_BYTES;
#pragma unroll
        for (int q = 0; q < 2; q++) {
            int ix = tid * 2 + q;
            int row = ix >> 2;
            int ch  = ix & 3;
            long arow = bm + row;
            long arc = arow < (M - 1) ? arow : (M - 1);
            cp16(sa + row * 80 + ch * 16, Ag + arc * 256 + kc * 32 + ch * 8,
                 (arow < M) ? 16u : 0u);
            cp16(sb + row * 80 + ch * 16, B + (long)(bn + row) * 256 + kc * 32 + ch * 8, 16u);
        }
        cp_commit();
    };

    issue(0);
    issue(1);

    for (int it = 0; it < NITER; it++) {
        cp_wait1();
        __syncthreads();
        if (it + 2 < NITER) issue(it + 2);

        const uint32_t sa = sbase + (it % STAGES) * STAGE_BYTES;
        const uint32_t sb = sa + TILE_BYTES;
#pragma unroll
        for (int ks = 0; ks < 2; ks++) {
            uint32_t a[4][4];
#pragma unroll
            for (int mt = 0; mt < 4; mt++)
                ldmx4(a[mt], sa + (wm + mt * 16 + (lane & 15)) * 80
                              + ks * 32 + (lane >> 4) * 16);
            uint32_t b[2][4];
#pragma unroll
            for (int jb = 0; jb < 2; jb++)
                ldmx4(b[jb], sb + (wn + jb * 16 + ((lane >> 4) << 3) + (lane & 7)) * 80
                              + ks * 32 + ((lane >> 3) & 1) * 16);
#pragma unroll
            for (int mt = 0; mt < 4; mt++)
#pragma unroll
                for (int nt = 0; nt < 4; nt++)
                    mma16816(acc[mt][nt], a[mt],
                             b[nt >> 1][(nt & 1) * 2], b[nt >> 1][(nt & 1) * 2 + 1]);
        }
        __syncthreads();
    }
    cp_wait0();

    // epilogue (+ fused attention dots)
    float* elacc = reinterpret_cast<float*>(smem + STAGES * STAGE_BYTES);
    float* eracc = elacc + 256;
    float alv[8], arv[8];
    float pel[4][2] = {}, per_[4][2] = {};
    if (al) {
        elacc[tid] = 0.f; eracc[tid] = 0.f;
        __syncthreads();
#pragma unroll
        for (int nt = 0; nt < 4; nt++) {
            int c0 = bn + wn + nt * 8 + (lane & 3) * 2;
            alv[nt * 2]     = al[c0];
            alv[nt * 2 + 1] = al[c0 + 1];
            arv[nt * 2]     = ar[c0];
            arv[nt * 2 + 1] = ar[c0 + 1];
        }
    }

    const bool even = ((Ncols & 1) == 0);
#pragma unroll
    for (int mt = 0; mt < 4; mt++) {
#pragma unroll
        for (int nt = 0; nt < 4; nt++) {
            int c0 = bn + wn + nt * 8 + (lane & 3) * 2;
            float b0 = 0.f, b1 = 0.f;
            if (bias) {
                if (c0 < Ncols)     b0 = bias[c0];
                if (c0 + 1 < Ncols) b1 = bias[c0 + 1];
            }
#pragma unroll
            for (int half = 0; half < 2; half++) {
                long row = bm + wm + mt * 16 + (lane >> 2) + half * 8;
                float v0 = acc[mt][nt][half * 2 + 0];
                float v1 = acc[mt][nt][half * 2 + 1];
                if (al) {
                    pel[mt][half]  += v0 * alv[nt * 2] + v1 * alv[nt * 2 + 1];
                    per_[mt][half] += v0 * arv[nt * 2] + v1 * arv[nt * 2 + 1];
                }
                if (row >= M) continue;
                v0 += b0; v1 += b1;
                float* crow = C + row * Ncols;
                if (even && (c0 + 1) < Ncols) {
                    *reinterpret_cast<float2*>(crow + c0) = make_float2(v0, v1);
                } else {
                    if (c0 < Ncols)     crow[c0] = v0;
                    if (c0 + 1 < Ncols) crow[c0 + 1] = v1;
                }
            }
        }
    }

    if (al) {
#pragma unroll
        for (int mt = 0; mt < 4; mt++)
#pragma unroll
            for (int half = 0; half < 2; half++) {
                float s1 = pel[mt][half], s2 = per_[mt][half];
                s1 += __shfl_xor_sync(0xffffffffu, s1, 1);
                s1 += __shfl_xor_sync(0xffffffffu, s1, 2);
                s2 += __shfl_xor_sync(0xffffffffu, s2, 1);
                s2 += __shfl_xor_sync(0xffffffffu, s2, 2);
                if ((lane & 3) == 0) {
                    int rl = wm + mt * 16 + (lane >> 2) + half * 8;
                    int hl = wn >> 6;
                    atomicAdd(&elacc[rl * 2 + hl], s1);
                    atomicAdd(&eracc[rl * 2 + hl], s2);
                }
            }
        __syncthreads();
        {
            int rl = tid >> 1, hl = tid & 1;
            long n = bm + rl;
            if (n < M) {
                int hg = (bn >> 6) + hl;
                elO[n * 4 + hg] = elacc[tid];
                erO[n * 4 + hg] = eracc[tid];
            }
        }
    }
}

// ---------------- CSR aggregation: one warp per dst node ----------------
// mode 0: agg = result; mode 1: agg += result;
// mode 2: out = (agg + result + bias), optional relu, fp16 hi/lo split
__global__ void __launch_bounds__(256) agg_csr(
    const int* __restrict__ rowptr_e, const int* __restrict__ ssorted,
    const float* __restrict__ el, const float* __restrict__ er,
    const float* __restrict__ feat, float* __restrict__ agg,
    int mode, const float* __restrict__ bias_l,
    __half* __restrict__ hi, __half* __restrict__ lo, int do_relu)
{
    int d = blockIdx.x * 8 + (threadIdx.x >> 5);
    if (d >= NODES) return;
    int lane = threadIdx.x & 31;
    int beg = rowptr_e[d], end = rowptr_e[d + 1];
    float erl = (lane < 4) ? er[(size_t)d * 4 + lane] : 0.f;
    int h0 = lane >> 4;

    float4 a0 = make_float4(0.f, 0.f, 0.f, 0.f);
    float4 a1 = make_float4(0.f, 0.f, 0.f, 0.f);
    float den = 0.f;

    for (int i = beg; i < end; i++) {
        int s = ssorted[i];
        float exv = 0.f;
        if (lane < 4) {
            float lg = el[(size_t)s * 4 + lane] + erl;
            lg = lg > 0.f ? lg : NEG_SLOPE * lg;
            exv = __expf(lg);
            den += exv;
        }
        float e0 = __shfl_sync(0xffffffffu, exv, h0);
        float e1 = __shfl_sync(0xffffffffu, exv, h0 + 2);
        const float4* fs = reinterpret_cast<const float4*>(feat + (size_t)s * FEAT);
        float4 f0 = fs[lane];
        float4 f1 = fs[lane + 32];
        a0.x += e0 * f0.x; a0.y += e0 * f0.y; a0.z += e0 * f0.z; a0.w += e0 * f0.w;
        a1.x += e1 * f1.x; a1.y += e1 * f1.y; a1.z += e1 * f1.z; a1.w += e1 * f1.w;
    }

    float d0 = __shfl_sync(0xffffffffu, den, h0);
    float d1 = __shfl_sync(0xffffffffu, den, h0 + 2);
    float r0 = (d0 > 0.f) ? (1.0f / d0) : 0.f;
    float r1 = (d1 > 0.f) ? (1.0f / d1) : 0.f;
    a0.x *= r0; a0.y *= r0; a0.z *= r0; a0.w *= r0;
    a1.x *= r1; a1.y *= r1; a1.z *= r1; a1.w *= r1;

    float4* ag = reinterpret_cast<float4*>(agg + (size_t)d * FEAT);
    if (mode >= 1) {
        float4 p0 = ag[lane], p1 = ag[lane + 32];
        a0.x += p0.x; a0.y += p0.y; a0.z += p0.z; a0.w += p0.w;
        a1.x += p1.x; a1.y += p1.y; a1.z += p1.z; a1.w += p1.w;
    }
    if (mode < 2) {
        ag[lane] = a0;
        ag[lane + 32] = a1;
        return;
    }

    // final etype: add summed bias, relu, fp16 split
    int c0 = lane * 4, c1 = 128 + lane * 4;
#pragma unroll
    for (int q = 0; q < 4; q++) {
        (&a0.x)[q] += bias_l[c0 + q] + bias_l[256 + c0 + q] + bias_l[512 + c0 + q];
        (&a1.x)[q] += bias_l[c1 + q] + bias_l[256 + c1 + q] + bias_l[512 + c1 + q];
    }
    if (do_relu) {
        a0.x = fmaxf(a0.x, 0.f); a0.y = fmaxf(a0.y, 0.f);
        a0.z = fmaxf(a0.z, 0.f); a0.w = fmaxf(a0.w, 0.f);
        a1.x = fmaxf(a1.x, 0.f); a1.y = fmaxf(a1.y, 0.f);
        a1.z = fmaxf(a1.z, 0.f); a1.w = fmaxf(a1.w, 0.f);
    }
    __half2* ph = reinterpret_cast<__half2*>(hi + (size_t)d * FEAT);
    __half2* pl = reinterpret_cast<__half2*>(lo + (size_t)d * FEAT);
#pragma unroll
    for (int q = 0; q < 2; q++) {
        float4 v = q ? a1 : a0;
        int base = (q ? c1 : c0) >> 1;
        __half hh0 = __float2half_rn(v.x), hh1 = __float2half_rn(v.y);
        __half hh2 = __float2half_rn(v.z), hh3 = __float2half_rn(v.w);
        ph[base]     = __halves2half2(hh0, hh1);
        ph[base + 1] = __halves2half2(hh2, hh3);
        pl[base]     = __halves2half2(__float2half_rn(v.x - __half2float(hh0)),
                                      __float2half_rn(v.y - __half2float(hh1)));
        pl[base + 1] = __halves2half2(__float2half_rn(v.z - __half2float(hh2)),
                                      __float2half_rn(v.w - __half2float(hh3)));
    }
}

// ---------------- launch ----------------
extern "C" void kernel_launch(void* const* d_in, const int* in_sizes, int n_in,
                              void* d_out, int out_size)
{
    const float* x      = (const float*)d_in[0];
    const float* W      = (const float*)d_in[1];
    const float* attn_l = (const float*)d_in[2];
    const float* attn_r = (const float*)d_in[3];
    const float* bias   = (const float*)d_in[4];
    const float* W_out  = (const float*)d_in[5];
    const float* b_out  = (const float*)d_in[6];
    const int*   src    = (const int*)d_in[7];
    const int*   dst    = (const int*)d_in[8];

    float *feat, *agg, *el, *er;
    __half *ahi, *alo, *whi, *wohi;
    int *rowptr, *head, *blksum, *ssorted;
    cudaGetSymbolAddress((void**)&feat,    g_feat);
    cudaGetSymbolAddress((void**)&agg,     g_agg);
    cudaGetSymbolAddress((void**)&el,      g_el);
    cudaGetSymbolAddress((void**)&er,      g_er);
    cudaGetSymbolAddress((void**)&ahi,     g_ahi);
    cudaGetSymbolAddress((void**)&alo,     g_alo);
    cudaGetSymbolAddress((void**)&whi,     g_whi);
    cudaGetSymbolAddress((void**)&wohi,    g_wohi);
    cudaGetSymbolAddress((void**)&rowptr,  g_rowptr);
    cudaGetSymbolAddress((void**)&head,    g_head);
    cudaGetSymbolAddress((void**)&blksum,  g_blksum);
    cudaGetSymbolAddress((void**)&ssorted, g_ssorted);

    cudaFuncSetAttribute(gemm_mma, cudaFuncAttributeMaxDynamicSharedMemorySize, GEMM_SMEM);

    // prep + CSR build (head doubles as counts buffer initially)
    prep_w<<<(6 * FEAT * FEAT + 255) / 256, 256>>>(W, whi);
    prep_wout<<<(NPAD_OUT * FEAT + 255) / 256, 256>>>(W_out, wohi);
    split_f32<<<(NODES * FEAT / 4 + 255) / 256, 256>>>(x, ahi, alo, NODES * FEAT / 4);

    zero_i<<<(NSEG + 255) / 256, 256>>>(head, NSEG);
    hist_k<<<(TOTE + 255) / 256, 256>>>(dst, head);
    scan_l1<<<NBLK, SBLK>>>(head, rowptr, blksum);
    scan_l2<<<1, 1024>>>(blksum, rowptr);
    scan_l3<<<(NSEG + 255) / 256, 256>>>(rowptr, blksum, head);
    scatter_k<<<(TOTE + 255) / 256, 256>>>(src, dst, head, ssorted);

    dim3 feat_grid(GRID_M, 2);
    dim3 out_grid(GRID_M, 3);
    const int AGG_BLOCKS = (NODES + 7) / 8;

    for (int l = 0; l < 2; l++) {
        for (int e = 0; e < 3; e++) {
            int le = l * 3 + e;
            gemm_mma<<<feat_grid, 256, GEMM_SMEM>>>(
                ahi, alo, whi + (size_t)le * FEAT * FEAT, feat, nullptr,
                NODES, FEAT,
                attn_l + le * FEAT, attn_r + le * FEAT, el, er);
            agg_csr<<<AGG_BLOCKS, 256>>>(
                rowptr + e * NODES, ssorted, el, er, feat, agg,
                e,                                    // mode: 0 write, 1 accum, 2 final
                bias + l * 3 * FEAT, ahi, alo, (l == 0) ? 1 : 0);
        }
    }

    gemm_mma<<<out_grid, 256, GEMM_SMEM>>>(
        ahi, alo, wohi, (float*)d_out, b_out, NODES, CLASSES,
        nullptr, nullptr, nullptr, nullptr);
}

// round 11
// speedup vs baseline: 1.9367x; 1.0225x over previous
#include <cuda_runtime.h>
#include <cuda_fp16.h>
#include <cstdint>

// ---------------- problem constants ----------------
constexpr int NODES  = 100000;
constexpr int EDGES  = 500000;
constexpr int FEAT   = 256;
constexpr int CLASSES = 349;
constexpr int NPAD_OUT = 384;
constexpr float NEG_SLOPE = 0.2f;
constexpr int GRID_M = (NODES + 127) / 128;   // 782

constexpr int TOTE = 3 * EDGES;               // 1.5M
constexpr int NSEG = 3 * NODES;               // 300k
constexpr int SBLK = 512;
constexpr int NBLK = (NSEG + SBLK - 1) / SBLK; // 586

// GEMM tiling
constexpr int STAGES = 3;
constexpr int TILE_BYTES = 128 * 80;
constexpr int STAGE_BYTES = 2 * TILE_BYTES;
constexpr int GEMM_SMEM = STAGES * STAGE_BYTES + 2048;

// ---------------- device scratch ----------------
__device__ float  g_feat[(size_t)2 * NODES * FEAT];   // double-buffered by etype parity
__device__ float  g_agg[(size_t)NODES * FEAT];
__device__ float  g_el[2 * NODES * 4];
__device__ float  g_er[2 * NODES * 4];
__device__ __half g_ahi[(size_t)NODES * FEAT];
__device__ __half g_alo[(size_t)NODES * FEAT];
__device__ __half g_whi[6 * FEAT * FEAT];
__device__ __half g_wohi[NPAD_OUT * FEAT];
__device__ int    g_rowptr[NSEG + 1];
__device__ int    g_head[NSEG];
__device__ int    g_blksum[NBLK];
__device__ int    g_ssorted[TOTE];

// ---------------- helpers ----------------
__device__ __forceinline__ uint32_t smem_u32(const void* p) {
    uint32_t a;
    asm("{ .reg .u64 t; cvta.to.shared.u64 t, %1; cvt.u32.u64 %0, t; }" : "=r"(a) : "l"(p));
    return a;
}
__device__ __forceinline__ void cp16(uint32_t dst, const void* src, uint32_t sz) {
    asm volatile("cp.async.cg.shared.global [%0], [%1], 16, %2;"
                 :: "r"(dst), "l"(src), "r"(sz) : "memory");
}
__device__ __forceinline__ void cp_commit() { asm volatile("cp.async.commit_group;" ::: "memory"); }
__device__ __forceinline__ void cp_wait1()  { asm volatile("cp.async.wait_group 1;" ::: "memory"); }
__device__ __forceinline__ void cp_wait0()  { asm volatile("cp.async.wait_group 0;" ::: "memory"); }

__device__ __forceinline__ void ldmx4(uint32_t* r, uint32_t addr) {
    asm volatile("ldmatrix.sync.aligned.m8n8.x4.shared.b16 {%0,%1,%2,%3}, [%4];"
                 : "=r"(r[0]), "=r"(r[1]), "=r"(r[2]), "=r"(r[3]) : "r"(addr));
}
__device__ __forceinline__ void mma16816(float* d, const uint32_t* a,
                                         uint32_t b0, uint32_t b1) {
    asm volatile(
        "mma.sync.aligned.m16n8k16.row.col.f32.f16.f16.f32 "
        "{%0,%1,%2,%3}, {%4,%5,%6,%7}, {%8,%9}, {%0,%1,%2,%3};"
        : "+f"(d[0]), "+f"(d[1]), "+f"(d[2]), "+f"(d[3])
        : "r"(a[0]), "r"(a[1]), "r"(a[2]), "r"(a[3]), "r"(b0), "r"(b1));
}

// ---------------- CSR build ----------------
__global__ void __launch_bounds__(256) zero_i(int* __restrict__ p, int n) {
    int i = blockIdx.x * 256 + threadIdx.x;
    if (i < n) p[i] = 0;
}

__global__ void __launch_bounds__(256) hist_k(const int* __restrict__ dst,
                                              int* __restrict__ counts) {
    int i = blockIdx.x * 256 + threadIdx.x;
    if (i >= TOTE) return;
    int e = i / EDGES;
    atomicAdd(&counts[e * NODES + dst[i]], 1);
}

__global__ void __launch_bounds__(SBLK) scan_l1(const int* __restrict__ counts,
                                                int* __restrict__ rowptr,
                                                int* __restrict__ blksum) {
    __shared__ int s[SBLK];
    int t = threadIdx.x, b = blockIdx.x, i = b * SBLK + t;
    int v = (i < NSEG) ? counts[i] : 0;
    s[t] = v;
    __syncthreads();
    for (int o = 1; o < SBLK; o <<= 1) {
        int x = (t >= o) ? s[t - o] : 0;
        __syncthreads();
        s[t] += x;
        __syncthreads();
    }
    if (i < NSEG) rowptr[i] = s[t] - v;
    if (t == SBLK - 1) blksum[b] = s[t];
}

__global__ void __launch_bounds__(1024) scan_l2(int* __restrict__ blksum,
                                                int* __restrict__ rowptr) {
    __shared__ int s[1024];
    int t = threadIdx.x;
    int v = (t < NBLK) ? blksum[t] : 0;
    s[t] = v;
    __syncthreads();
    for (int o = 1; o < 1024; o <<= 1) {
        int x = (t >= o) ? s[t - o] : 0;
        __syncthreads();
        s[t] += x;
        __syncthreads();
    }
    if (t < NBLK) blksum[t] = s[t] - v;
    if (t == 0) rowptr[NSEG] = TOTE;
}

__global__ void __launch_bounds__(256) scan_l3(int* __restrict__ rowptr,
                                               const int* __restrict__ blksum,
                                               int* __restrict__ head) {
    int i = blockIdx.x * 256 + threadIdx.x;
    if (i >= NSEG) return;
    int v = rowptr[i] + blksum[i / SBLK];
    rowptr[i] = v;
    head[i] = v;
}

__global__ void __launch_bounds__(256) scatter_k(const int* __restrict__ src,
                                                 const int* __restrict__ dst,
                                                 int* __restrict__ head,
                                                 int* __restrict__ ssorted) {
    int i = blockIdx.x * 256 + threadIdx.x;
    if (i >= TOTE) return;
    int e = i / EDGES;
    int pos = atomicAdd(&head[e * NODES + dst[i]], 1);
    ssorted[pos] = src[i];
}

// ---------------- prep kernels ----------------
__global__ void __launch_bounds__(256) split_f32(
    const float* __restrict__ in, __half* __restrict__ hi,
    __half* __restrict__ lo, int n4)
{
    int i = blockIdx.x * blockDim.x + threadIdx.x;
    if (i >= n4) return;
    float4 v = reinterpret_cast<const float4*>(in)[i];
    __half h0 = __float2half_rn(v.x), h1 = __float2half_rn(v.y);
    __half h2 = __float2half_rn(v.z), h3 = __float2half_rn(v.w);
    __half l0 = __float2half_rn(v.x - __half2float(h0));
    __half l1 = __float2half_rn(v.y - __half2float(h1));
    __half l2 = __float2half_rn(v.z - __half2float(h2));
    __half l3 = __float2half_rn(v.w - __half2float(h3));
    __half2* ph = reinterpret_cast<__half2*>(hi);
    __half2* pl = reinterpret_cast<__half2*>(lo);
    ph[i * 2]     = __halves2half2(h0, h1);
    ph[i * 2 + 1] = __halves2half2(h2, h3);
    pl[i * 2]     = __halves2half2(l0, l1);
    pl[i * 2 + 1] = __halves2half2(l2, l3);
}

__global__ void __launch_bounds__(256) prep_w(
    const float* __restrict__ W, __half* __restrict__ hi)
{
    int idx = blockIdx.x * blockDim.x + threadIdx.x;
    if (idx >= 6 * FEAT * FEAT) return;
    int le = idx >> 16;
    int r  = idx & 0xffff;
    int n  = r >> 8;
    int k  = r & 255;
    hi[le * FEAT * FEAT + n * FEAT + k] = __float2half_rn(W[le * FEAT * FEAT + k * FEAT + n]);
}

__global__ void __launch_bounds__(256) prep_wout(
    const float* __restrict__ W_out, __half* __restrict__ hi)
{
    int idx = blockIdx.x * blockDim.x + threadIdx.x;
    if (idx >= NPAD_OUT * FEAT) return;
    int n = idx >> 8;
    int k = idx & 255;
    float v = (n < CLASSES) ? W_out[k * CLASSES + n] : 0.f;
    hi[n * FEAT + k] = __float2half_rn(v);
}

// ---------------- tensor-core GEMM (+ fused attention dots) ----------------
__global__ void __launch_bounds__(256, 2) gemm_mma(
    const __half* __restrict__ Ahi, const __half* __restrict__ Alo,
    const __half* __restrict__ B, float* __restrict__ C,
    const float* __restrict__ bias, int M, int Ncols,
    const float* __restrict__ al, const float* __restrict__ ar,
    float* __restrict__ elO, float* __restrict__ erO)
{
    extern __shared__ char smem[];
    const uint32_t sbase = smem_u32(smem);
    const int tid = threadIdx.x;
    const int lane = tid & 31;
    const int warp = tid >> 5;
    const int wm = (warp & 1) * 64;
    const int wn = (warp >> 1) * 32;
    const long bm = (long)blockIdx.x * 128;
    const int bn  = blockIdx.y * 128;

    float acc[4][4][4];
#pragma unroll
    for (int i = 0; i < 4; i++)
#pragma unroll
        for (int j = 0; j < 4; j++)
#pragma unroll
            for (int q = 0; q < 4; q++) acc[i][j][q] = 0.f;

    const int NITER = 16;

    auto issue = [&](int it) {
        const int p  = it >> 3;
        const int kc = it & 7;
        const __half* Ag = (p == 0) ? Ahi : Alo;
        const uint32_t sa = sbase + (it % STAGES) * STAGE_BYTES;
        const uint32_t sb = sa + TILE_BYTES;
#pragma unroll
        for (int q = 0; q < 2; q++) {
            int ix = tid * 2 + q;
            int row = ix >> 2;
            int ch  = ix & 3;
            long arow = bm + row;
            long arc = arow < (M - 1) ? arow : (M - 1);
            cp16(sa + row * 80 + ch * 16, Ag + arc * 256 + kc * 32 + ch * 8,
                 (arow < M) ? 16u : 0u);
            cp16(sb + row * 80 + ch * 16, B + (long)(bn + row) * 256 + kc * 32 + ch * 8, 16u);
        }
        cp_commit();
    };

    issue(0);
    issue(1);

    for (int it = 0; it < NITER; it++) {
        cp_wait1();
        __syncthreads();
        if (it + 2 < NITER) issue(it + 2);

        const uint32_t sa = sbase + (it % STAGES) * STAGE_BYTES;
        const uint32_t sb = sa + TILE_BYTES;
#pragma unroll
        for (int ks = 0; ks < 2; ks++) {
            uint32_t a[4][4];
#pragma unroll
            for (int mt = 0; mt < 4; mt++)
                ldmx4(a[mt], sa + (wm + mt * 16 + (lane & 15)) * 80
                              + ks * 32 + (lane >> 4) * 16);
            uint32_t b[2][4];
#pragma unroll
            for (int jb = 0; jb < 2; jb++)
                ldmx4(b[jb], sb + (wn + jb * 16 + ((lane >> 4) << 3) + (lane & 7)) * 80
                              + ks * 32 + ((lane >> 3) & 1) * 16);
#pragma unroll
            for (int mt = 0; mt < 4; mt++)
#pragma unroll
                for (int nt = 0; nt < 4; nt++)
                    mma16816(acc[mt][nt], a[mt],
                             b[nt >> 1][(nt & 1) * 2], b[nt >> 1][(nt & 1) * 2 + 1]);
        }
        __syncthreads();
    }
    cp_wait0();

    // epilogue (+ fused attention dots)
    float* elacc = reinterpret_cast<float*>(smem + STAGES * STAGE_BYTES);
    float* eracc = elacc + 256;
    float alv[8], arv[8];
    float pel[4][2] = {}, per_[4][2] = {};
    if (al) {
        elacc[tid] = 0.f; eracc[tid] = 0.f;
        __syncthreads();
#pragma unroll
        for (int nt = 0; nt < 4; nt++) {
            int c0 = bn + wn + nt * 8 + (lane & 3) * 2;
            alv[nt * 2]     = al[c0];
            alv[nt * 2 + 1] = al[c0 + 1];
            arv[nt * 2]     = ar[c0];
            arv[nt * 2 + 1] = ar[c0 + 1];
        }
    }

    const bool even = ((Ncols & 1) == 0);
#pragma unroll
    for (int mt = 0; mt < 4; mt++) {
#pragma unroll
        for (int nt = 0; nt < 4; nt++) {
            int c0 = bn + wn + nt * 8 + (lane & 3) * 2;
            float b0 = 0.f, b1 = 0.f;
            if (bias) {
                if (c0 < Ncols)     b0 = bias[c0];
                if (c0 + 1 < Ncols) b1 = bias[c0 + 1];
            }
#pragma unroll
            for (int half = 0; half < 2; half++) {
                long row = bm + wm + mt * 16 + (lane >> 2) + half * 8;
                float v0 = acc[mt][nt][half * 2 + 0];
                float v1 = acc[mt][nt][half * 2 + 1];
                if (al) {
                    pel[mt][half]  += v0 * alv[nt * 2] + v1 * alv[nt * 2 + 1];
                    per_[mt][half] += v0 * arv[nt * 2] + v1 * arv[nt * 2 + 1];
                }
                if (row >= M) continue;
                v0 += b0; v1 += b1;
                float* crow = C + row * Ncols;
                if (even && (c0 + 1) < Ncols) {
                    *reinterpret_cast<float2*>(crow + c0) = make_float2(v0, v1);
                } else {
                    if (c0 < Ncols)     crow[c0] = v0;
                    if (c0 + 1 < Ncols) crow[c0 + 1] = v1;
                }
            }
        }
    }

    if (al) {
#pragma unroll
        for (int mt = 0; mt < 4; mt++)
#pragma unroll
            for (int half = 0; half < 2; half++) {
                float s1 = pel[mt][half], s2 = per_[mt][half];
                s1 += __shfl_xor_sync(0xffffffffu, s1, 1);
                s1 += __shfl_xor_sync(0xffffffffu, s1, 2);
                s2 += __shfl_xor_sync(0xffffffffu, s2, 1);
                s2 += __shfl_xor_sync(0xffffffffu, s2, 2);
                if ((lane & 3) == 0) {
                    int rl = wm + mt * 16 + (lane >> 2) + half * 8;
                    int hl = wn >> 6;
                    atomicAdd(&elacc[rl * 2 + hl], s1);
                    atomicAdd(&eracc[rl * 2 + hl], s2);
                }
            }
        __syncthreads();
        {
            int rl = tid >> 1, hl = tid & 1;
            long n = bm + rl;
            if (n < M) {
                int hg = (bn >> 6) + hl;
                elO[n * 4 + hg] = elacc[tid];
                erO[n * 4 + hg] = eracc[tid];
            }
        }
    }
}

// ---------------- CSR aggregation: one warp per dst node ----------------
__global__ void __launch_bounds__(256) agg_csr(
    const int* __restrict__ rowptr_e, const int* __restrict__ ssorted,
    const float* __restrict__ el, const float* __restrict__ er,
    const float* __restrict__ feat, float* __restrict__ agg,
    int mode, const float* __restrict__ bias_l,
    __half* __restrict__ hi, __half* __restrict__ lo, int do_relu)
{
    int d = blockIdx.x * 8 + (threadIdx.x >> 5);
    if (d >= NODES) return;
    int lane = threadIdx.x & 31;
    int beg = rowptr_e[d], end = rowptr_e[d + 1];
    float erl = (lane < 4) ? er[(size_t)d * 4 + lane] : 0.f;
    int h0 = lane >> 4;

    float4 a0 = make_float4(0.f, 0.f, 0.f, 0.f);
    float4 a1 = make_float4(0.f, 0.f, 0.f, 0.f);
    float den = 0.f;

    for (int i = beg; i < end; i++) {
        int s = ssorted[i];
        float exv = 0.f;
        if (lane < 4) {
            float lg = el[(size_t)s * 4 + lane] + erl;
            lg = lg > 0.f ? lg : NEG_SLOPE * lg;
            exv = __expf(lg);
            den += exv;
        }
        float e0 = __shfl_sync(0xffffffffu, exv, h0);
        float e1 = __shfl_sync(0xffffffffu, exv, h0 + 2);
        const float4* fs = reinterpret_cast<const float4*>(feat + (size_t)s * FEAT);
        float4 f0 = fs[lane];
        float4 f1 = fs[lane + 32];
        a0.x += e0 * f0.x; a0.y += e0 * f0.y; a0.z += e0 * f0.z; a0.w += e0 * f0.w;
        a1.x += e1 * f1.x; a1.y += e1 * f1.y; a1.z += e1 * f1.z; a1.w += e1 * f1.w;
    }

    float d0 = __shfl_sync(0xffffffffu, den, h0);
    float d1 = __shfl_sync(0xffffffffu, den, h0 + 2);
    float r0 = (d0 > 0.f) ? (1.0f / d0) : 0.f;
    float r1 = (d1 > 0.f) ? (1.0f / d1) : 0.f;
    a0.x *= r0; a0.y *= r0; a0.z *= r0; a0.w *= r0;
    a1.x *= r1; a1.y *= r1; a1.z *= r1; a1.w *= r1;

    float4* ag = reinterpret_cast<float4*>(agg + (size_t)d * FEAT);
    if (mode >= 1) {
        float4 p0 = ag[lane], p1 = ag[lane + 32];
        a0.x += p0.x; a0.y += p0.y; a0.z += p0.z; a0.w += p0.w;
        a1.x += p1.x; a1.y += p1.y; a1.z += p1.z; a1.w += p1.w;
    }
    if (mode < 2) {
        ag[lane] = a0;
        ag[lane + 32] = a1;
        return;
    }

    int c0 = lane * 4, c1 = 128 + lane * 4;
#pragma unroll
    for (int q = 0; q < 4; q++) {
        (&a0.x)[q] += bias_l[c0 + q] + bias_l[256 + c0 + q] + bias_l[512 + c0 + q];
        (&a1.x)[q] += bias_l[c1 + q] + bias_l[256 + c1 + q] + bias_l[512 + c1 + q];
    }
    if (do_relu) {
        a0.x = fmaxf(a0.x, 0.f); a0.y = fmaxf(a0.y, 0.f);
        a0.z = fmaxf(a0.z, 0.f); a0.w = fmaxf(a0.w, 0.f);
        a1.x = fmaxf(a1.x, 0.f); a1.y = fmaxf(a1.y, 0.f);
        a1.z = fmaxf(a1.z, 0.f); a1.w = fmaxf(a1.w, 0.f);
    }
    __half2* ph = reinterpret_cast<__half2*>(hi + (size_t)d * FEAT);
    __half2* pl = reinterpret_cast<__half2*>(lo + (size_t)d * FEAT);
#pragma unroll
    for (int q = 0; q < 2; q++) {
        float4 v = q ? a1 : a0;
        int base = (q ? c1 : c0) >> 1;
        __half hh0 = __float2half_rn(v.x), hh1 = __float2half_rn(v.y);
        __half hh2 = __float2half_rn(v.z), hh3 = __float2half_rn(v.w);
        ph[base]     = __halves2half2(hh0, hh1);
        ph[base + 1] = __halves2half2(hh2, hh3);
        pl[base]     = __halves2half2(__float2half_rn(v.x - __half2float(hh0)),
                                      __float2half_rn(v.y - __half2float(hh1)));
        pl[base + 1] = __halves2half2(__float2half_rn(v.z - __half2float(hh2)),
                                      __float2half_rn(v.w - __half2float(hh3)));
    }
}

// ---------------- launch ----------------
extern "C" void kernel_launch(void* const* d_in, const int* in_sizes, int n_in,
                              void* d_out, int out_size)
{
    const float* x      = (const float*)d_in[0];
    const float* W      = (const float*)d_in[1];
    const float* attn_l = (const float*)d_in[2];
    const float* attn_r = (const float*)d_in[3];
    const float* bias   = (const float*)d_in[4];
    const float* W_out  = (const float*)d_in[5];
    const float* b_out  = (const float*)d_in[6];
    const int*   src    = (const int*)d_in[7];
    const int*   dst    = (const int*)d_in[8];

    float *feat, *agg, *el, *er;
    __half *ahi, *alo, *whi, *wohi;
    int *rowptr, *head, *blksum, *ssorted;
    cudaGetSymbolAddress((void**)&feat,    g_feat);
    cudaGetSymbolAddress((void**)&agg,     g_agg);
    cudaGetSymbolAddress((void**)&el,      g_el);
    cudaGetSymbolAddress((void**)&er,      g_er);
    cudaGetSymbolAddress((void**)&ahi,     g_ahi);
    cudaGetSymbolAddress((void**)&alo,     g_alo);
    cudaGetSymbolAddress((void**)&whi,     g_whi);
    cudaGetSymbolAddress((void**)&wohi,    g_wohi);
    cudaGetSymbolAddress((void**)&rowptr,  g_rowptr);
    cudaGetSymbolAddress((void**)&head,    g_head);
    cudaGetSymbolAddress((void**)&blksum,  g_blksum);
    cudaGetSymbolAddress((void**)&ssorted, g_ssorted);

    cudaFuncSetAttribute(gemm_mma, cudaFuncAttributeMaxDynamicSharedMemorySize, GEMM_SMEM);

    // lazy one-time stream/event setup (first call = uncaptured correctness run)
    static cudaStream_t s1 = nullptr;
    static cudaEvent_t evStart, evGemm[6], evAgg[6], evLayer[2];
    if (!s1) {
        cudaStreamCreateWithFlags(&s1, cudaStreamNonBlocking);
        cudaEventCreateWithFlags(&evStart, cudaEventDisableTiming);
        for (int i = 0; i < 6; i++) {
            cudaEventCreateWithFlags(&evGemm[i], cudaEventDisableTiming);
            cudaEventCreateWithFlags(&evAgg[i],  cudaEventDisableTiming);
        }
        for (int i = 0; i < 2; i++) cudaEventCreateWithFlags(&evLayer[i], cudaEventDisableTiming);
    }

    // fork side stream from capture stream
    cudaEventRecord(evStart, 0);
    cudaStreamWaitEvent(s1, evStart, 0);

    // main stream: weight/input prep
    prep_w<<<(6 * FEAT * FEAT + 255) / 256, 256>>>(W, whi);
    prep_wout<<<(NPAD_OUT * FEAT + 255) / 256, 256>>>(W_out, wohi);
    split_f32<<<(NODES * FEAT / 4 + 255) / 256, 256>>>(x, ahi, alo, NODES * FEAT / 4);

    // side stream: CSR build (overlaps prep + first GEMM)
    zero_i<<<(NSEG + 255) / 256, 256, 0, s1>>>(head, NSEG);
    hist_k<<<(TOTE + 255) / 256, 256, 0, s1>>>(dst, head);
    scan_l1<<<NBLK, SBLK, 0, s1>>>(head, rowptr, blksum);
    scan_l2<<<1, 1024, 0, s1>>>(blksum, rowptr);
    scan_l3<<<(NSEG + 255) / 256, 256, 0, s1>>>(rowptr, blksum, head);
    scatter_k<<<(TOTE + 255) / 256, 256, 0, s1>>>(src, dst, head, ssorted);

    dim3 feat_grid(GRID_M, 2);
    dim3 out_grid(GRID_M, 3);
    const int AGG_BLOCKS = (NODES + 7) / 8;

    for (int l = 0; l < 2; l++) {
        for (int e = 0; e < 3; e++) {
            int le = l * 3 + e;
            int pb = e & 1;
            float* feat_e = feat + (size_t)pb * NODES * FEAT;
            float* el_e = el + (size_t)pb * NODES * 4;
            float* er_e = er + (size_t)pb * NODES * 4;
            // ANTI-RACE: gemm(e=2) reuses parity-0 buffers still being read by agg(e=0)
            if (e == 2) cudaStreamWaitEvent(0, evAgg[l * 3], 0);
            // main stream: GEMM for etype e (writes parity-pb buffers)
            gemm_mma<<<feat_grid, 256, GEMM_SMEM>>>(
                ahi, alo, whi + (size_t)le * FEAT * FEAT, feat_e, nullptr,
                NODES, FEAT,
                attn_l + le * FEAT, attn_r + le * FEAT, el_e, er_e);
            cudaEventRecord(evGemm[le], 0);
            // side stream: aggregation for etype e (serialized among themselves on s1)
            cudaStreamWaitEvent(s1, evGemm[le], 0);
            agg_csr<<<AGG_BLOCKS, 256, 0, s1>>>(
                rowptr + e * NODES, ssorted, el_e, er_e, feat_e, agg,
                e, bias + l * 3 * FEAT, ahi, alo, (l == 0) ? 1 : 0);
            cudaEventRecord(evAgg[le], s1);
        }
        // layer boundary: main must wait for agg2 (writes ahi/alo)
        cudaEventRecord(evLayer[l], s1);
        cudaStreamWaitEvent(0, evLayer[l], 0);
    }

    gemm_mma<<<out_grid, 256, GEMM_SMEM>>>(
        ahi, alo, wohi, (float*)d_out, b_out, NODES, CLASSES,
        nullptr, nullptr, nullptr, nullptr);
}